// round 8
// baseline (speedup 1.0000x reference)
#include <cuda_runtime.h>
#include <cuda_bf16.h>
#include <cooperative_groups.h>

namespace cg = cooperative_groups;

#define D    256
#define F    1024
#define NL   4
#define NC   10
#define CS   8
#define TPB  256

__device__ __forceinline__ float2 blockReduceSum2(float a, float b, float2* red2) {
    #pragma unroll
    for (int o = 16; o > 0; o >>= 1) {
        a += __shfl_xor_sync(0xffffffffu, a, o);
        b += __shfl_xor_sync(0xffffffffu, b, o);
    }
    int wid = threadIdx.x >> 5;
    if ((threadIdx.x & 31) == 0) red2[wid] = make_float2(a, b);
    __syncthreads();
    if (threadIdx.x < 8) {
        float2 t = red2[threadIdx.x];
        #pragma unroll
        for (int o = 4; o > 0; o >>= 1) {
            t.x += __shfl_xor_sync(0xffu, t.x, o);
            t.y += __shfl_xor_sync(0xffu, t.y, o);
        }
        if (threadIdx.x == 0) red2[0] = t;
    }
    __syncthreads();
    float2 r = red2[0];
    __syncthreads();
    return r;
}

__device__ __forceinline__ float gelu_tanh(float x) {
    const float c = 0.7978845608028654f;
    float u = c * (x + 0.044715f * x * x * x);
    return 0.5f * x * (1.0f + tanhf(u));
}

__global__ void __launch_bounds__(TPB, 1) __cluster_dims__(CS, 1, 1)
performer_cls_kernel(const int*   __restrict__ xx,
                     const float* __restrict__ emb_tok,
                     const float* __restrict__ emb_pos,
                     const float* __restrict__ ln1_s,
                     const float* __restrict__ ln1_b,
                     const float* __restrict__ wv,
                     const float* __restrict__ wo,
                     const float* __restrict__ bo,
                     const float* __restrict__ ln2_s,
                     const float* __restrict__ ln2_b,
                     const float* __restrict__ w1,
                     const float* __restrict__ b1v,
                     const float* __restrict__ w2,
                     const float* __restrict__ b2v,
                     const float* __restrict__ wcls,
                     const float* __restrict__ bcls,
                     float* __restrict__ out,
                     int N)
{
    __shared__ float  sh_y[D];        // LN output (replicated per rank)
    __shared__ float  sh_v0[32];      // my v0 chunk
    __shared__ float  sh_gc[128];     // my gelu-hidden chunk
    __shared__ float  ps[288];        // split-K partials
    __shared__ float  ar_a[CS * D];   // all-reduce slots, attention stage
    __shared__ float  ar_b[CS * D];   // all-reduce slots, MLP stage
    __shared__ float2 red2[8];

    cg::cluster_group cluster = cg::this_cluster();
    const int tid = threadIdx.x;
    const int r   = (int)cluster.block_rank();   // 0..7
    const int b   = blockIdx.x >> 3;             // batch element

    const int jA  = tid & 31;                    // stage-A col within 32-chunk
    const int sA  = tid >> 5;                    // stage-A K-slice 0..7 (32 each)
    const int jB  = tid & 127;                   // stage-B col within 128-chunk
    const int sB  = tid >> 7;                    // stage-B K-slice 0..1 (128 each)
    const int j0  = r * 32;                      // attention col-chunk base
    const int j0b = r * 128;                     // MLP col-chunk base

    // ---- init: every rank computes full h0 locally (one elem/thread) ----
    float hv;
    {
        const int tok = xx[b * N];
        hv = emb_tok[tok * D + tid] + emb_pos[tid];
    }

    for (int l = 0; l < NL; ++l) {
        // ================= fused attention stage =================
        {
            // LN1
            float2 ss = blockReduceSum2(hv, hv * hv, red2);
            float mu  = ss.x * (1.0f / D);
            float var = ss.y * (1.0f / D) - mu * mu;
            float inv = rsqrtf(var + 1e-5f);
            sh_y[tid] = (hv - mu) * inv * ln1_s[l * D + tid] + ln1_b[l * D + tid];
            __syncthreads();

            // v0_chunk[jA] partial over K-slice sA (32 rows)
            const float* Wv = wv + (size_t)l * D * D;
            float acc = 0.0f;
            #pragma unroll 8
            for (int i = 0; i < 32; ++i) {
                int k = sA * 32 + i;
                acc = fmaf(sh_y[k], Wv[(size_t)k * D + j0 + jA], acc);
            }
            ps[jA * 9 + sA] = acc;

            // prefetch my wo column (rows j0..j0+31, col tid) into registers
            const float* Wo = wo + (size_t)l * D * D;
            float wpre[32];
            #pragma unroll
            for (int i = 0; i < 32; ++i)
                wpre[i] = Wo[(size_t)(j0 + i) * D + tid];

            __syncthreads();
            if (tid < 32) {
                float v = 0.0f;
                #pragma unroll
                for (int s = 0; s < 8; ++s) v += ps[tid * 9 + s];
                sh_v0[tid] = v;
            }
            __syncthreads();

            // partial_o[tid] = v0_chunk . wo[chunk rows, tid]  (all local)
            float po = 0.0f;
            #pragma unroll
            for (int i = 0; i < 32; ++i)
                po = fmaf(sh_v0[i], wpre[i], po);

            // all-reduce: write my partial into slot r of every rank
            #pragma unroll
            for (int rk = 0; rk < CS; ++rk) {
                float* dst = cluster.map_shared_rank(ar_a, rk);
                dst[r * D + tid] = po;
            }
        }
        cluster.sync();
        {
            float o = bo[l * D + tid];
            #pragma unroll
            for (int rk = 0; rk < CS; ++rk) o += ar_a[rk * D + tid];
            hv += o;
        }

        // ================= fused MLP stage =================
        {
            // LN2
            float2 ss = blockReduceSum2(hv, hv * hv, red2);
            float mu  = ss.x * (1.0f / D);
            float var = ss.y * (1.0f / D) - mu * mu;
            float inv = rsqrtf(var + 1e-5f);
            sh_y[tid] = (hv - mu) * inv * ln2_s[l * D + tid] + ln2_b[l * D + tid];
            __syncthreads();

            // g_chunk[jB] partial over K-slice sB (128 rows)
            const float* W1 = w1 + (size_t)l * D * F;
            float acc = 0.0f;
            #pragma unroll 16
            for (int i = 0; i < 128; ++i) {
                int k = sB * 128 + i;
                acc = fmaf(sh_y[k], W1[(size_t)k * F + j0b + jB], acc);
            }
            ps[sB * 128 + jB] = acc;
            __syncthreads();
            if (tid < 128) {
                float g = ps[tid] + ps[128 + tid] + b1v[l * F + j0b + tid];
                sh_gc[tid] = gelu_tanh(g);
            }
            __syncthreads();

            // partial[tid] = g_chunk . w2[chunk rows, tid]  (all local)
            const float* W2 = w2 + (size_t)l * F * D;
            float po = 0.0f;
            #pragma unroll 16
            for (int i = 0; i < 128; ++i)
                po = fmaf(sh_gc[i], W2[(size_t)(j0b + i) * D + tid], po);

            #pragma unroll
            for (int rk = 0; rk < CS; ++rk) {
                float* dst = cluster.map_shared_rank(ar_b, rk);
                dst[r * D + tid] = po;
            }
        }
        cluster.sync();
        {
            float dlt = b2v[l * D + tid];
            #pragma unroll
            for (int rk = 0; rk < CS; ++rk) dlt += ar_b[rk * D + tid];
            hv += dlt;
        }
    }

    // ================= classifier (rank 0) =================
    if (r == 0) {
        sh_y[tid] = hv;
        __syncthreads();
        if (tid < 160) {
            const int c = tid >> 4;          // class 0..9
            const int s = tid & 15;          // 16 K-slices of 16
            float acc = 0.0f;
            #pragma unroll
            for (int i = 0; i < 16; ++i) {
                int k = s * 16 + i;
                acc = fmaf(sh_y[k], wcls[k * NC + c], acc);
            }
            ps[c * 17 + s] = acc;
        }
        __syncthreads();
        if (tid < NC) {
            float acc = bcls[tid];
            #pragma unroll
            for (int s = 0; s < 16; ++s) acc += ps[tid * 17 + s];
            out[b * NC + tid] = acc;
        }
    }
}

extern "C" void kernel_launch(void* const* d_in, const int* in_sizes, int n_in,
                              void* d_out, int out_size)
{
    const int*   xx      = (const int*)  d_in[0];
    const float* emb_tok = (const float*)d_in[1];
    const float* emb_pos = (const float*)d_in[2];
    const float* ln1_s   = (const float*)d_in[4];
    const float* ln1_b   = (const float*)d_in[5];
    const float* wv      = (const float*)d_in[8];
    const float* wo      = (const float*)d_in[9];
    const float* bo      = (const float*)d_in[10];
    const float* ln2_s   = (const float*)d_in[11];
    const float* ln2_b   = (const float*)d_in[12];
    const float* w1      = (const float*)d_in[13];
    const float* b1v     = (const float*)d_in[14];
    const float* w2      = (const float*)d_in[15];
    const float* b2v     = (const float*)d_in[16];
    const float* wcls    = (const float*)d_in[17];
    const float* bcls    = (const float*)d_in[18];
    float* out = (float*)d_out;

    const int B = out_size / NC;      // 16
    const int N = in_sizes[0] / B;    // 4096

    performer_cls_kernel<<<B * CS, TPB>>>(xx, emb_tok, emb_pos, ln1_s, ln1_b,
                                          wv, wo, bo, ln2_s, ln2_b,
                                          w1, b1v, w2, b2v, wcls, bcls, out, N);
}

// round 9
// speedup vs baseline: 1.8878x; 1.8878x over previous
#include <cuda_runtime.h>
#include <cuda_bf16.h>
#include <cooperative_groups.h>

namespace cg = cooperative_groups;

#define D    256
#define F    1024
#define NL   4
#define NC   10
#define CS   8
#define TPB  256
#define M    4      // batch elements per cluster

__device__ __forceinline__ float gelu_tanh(float x) {
    const float c = 0.7978845608028654f;
    float u = c * (x + 0.044715f * x * x * x);
    return 0.5f * x * (1.0f + tanhf(u));
}

__global__ void __launch_bounds__(TPB, 1) __cluster_dims__(CS, 1, 1)
performer_cls_kernel(const int*   __restrict__ xx,
                     const float* __restrict__ emb_tok,
                     const float* __restrict__ emb_pos,
                     const float* __restrict__ ln1_s,
                     const float* __restrict__ ln1_b,
                     const float* __restrict__ wv,
                     const float* __restrict__ wo,
                     const float* __restrict__ bo,
                     const float* __restrict__ ln2_s,
                     const float* __restrict__ ln2_b,
                     const float* __restrict__ w1,
                     const float* __restrict__ b1v,
                     const float* __restrict__ w2,
                     const float* __restrict__ b2v,
                     const float* __restrict__ wcls,
                     const float* __restrict__ bcls,
                     float* __restrict__ out,
                     int N)
{
    __shared__ float  sh_y[M * D];     // LN output (replicated per rank)
    __shared__ float  sh_v[M * D];     // v0, assembled from rank chunks
    __shared__ float  sh_g[M * F];     // MLP hidden, assembled
    __shared__ float  sh_o[M * D];     // o / mlp-delta, assembled
    __shared__ float  sh_c[M * 128];   // my chunk staging
    __shared__ float4 ps4[1056];       // split-K partials
    __shared__ float  red[80];

    float* psf = (float*)ps4;

    cg::cluster_group cluster = cg::this_cluster();
    const int tid = threadIdx.x;
    const int r   = (int)cluster.block_rank();   // 0..7
    const int b0  = (blockIdx.x >> 3) * M;       // first batch of this cluster

    const int c4  = tid & 7;            // A/C: float4-col within 8-group
    const int ks  = tid >> 3;           // A/C: K-slice 0..31
    const int c4b = tid & 31;           // B: float4-col within 32-group
    const int ksb = tid >> 5;           // B: K-slice 0..7
    const int j0  = r * 32;             // A/C col-chunk base (floats)
    const int j0b = r * 128;            // B col-chunk base (floats)
    const int rk   = tid >> 5;          // broadcast target rank
    const int lane = tid & 31;

    // ---------- LN helper (4 batches at once) ----------
    auto layer_norm = [&](const float* hv, const float* sc, const float* bi) {
        float s[M], q[M];
        #pragma unroll
        for (int m = 0; m < M; ++m) { s[m] = hv[m]; q[m] = hv[m] * hv[m]; }
        #pragma unroll
        for (int o = 16; o > 0; o >>= 1) {
            #pragma unroll
            for (int m = 0; m < M; ++m) {
                s[m] += __shfl_xor_sync(0xffffffffu, s[m], o);
                q[m] += __shfl_xor_sync(0xffffffffu, q[m], o);
            }
        }
        int wid = tid >> 5;
        if ((tid & 31) == 0) {
            #pragma unroll
            for (int m = 0; m < M; ++m) {
                red[wid * 8 + m]     = s[m];
                red[wid * 8 + 4 + m] = q[m];
            }
        }
        __syncthreads();
        if (tid < 8) {
            float acc = 0.0f;
            #pragma unroll
            for (int w = 0; w < 8; ++w) acc += red[w * 8 + tid];
            red[64 + tid] = acc;
        }
        __syncthreads();
        #pragma unroll
        for (int m = 0; m < M; ++m) {
            float mu  = red[64 + m] * (1.0f / D);
            float var = red[64 + 4 + m] * (1.0f / D) - mu * mu;
            float inv = rsqrtf(var + 1e-5f);
            sh_y[m * D + tid] = (hv[m] - mu) * inv * sc[tid] + bi[tid];
        }
        __syncthreads();
    };

    // ---------- D x D chunk matvec (A stages): in[M*D] -> my 32 cols ----------
    auto matvecA = [&](const float* in, const float4* W4) {
        float4 a[M];
        #pragma unroll
        for (int m = 0; m < M; ++m) a[m] = make_float4(0.f, 0.f, 0.f, 0.f);
        #pragma unroll
        for (int i = 0; i < 8; ++i) {
            int k = ks * 8 + i;
            float4 w = W4[k * 64 + r * 8 + c4];
            #pragma unroll
            for (int m = 0; m < M; ++m) {
                float yk = in[m * D + k];
                a[m].x = fmaf(yk, w.x, a[m].x); a[m].y = fmaf(yk, w.y, a[m].y);
                a[m].z = fmaf(yk, w.z, a[m].z); a[m].w = fmaf(yk, w.w, a[m].w);
            }
        }
        #pragma unroll
        for (int m = 0; m < M; ++m) ps4[ks * 33 + m * 8 + c4] = a[m];
        __syncthreads();
        if (tid < 128) {
            int m = tid >> 5, col = tid & 31;
            float acc = 0.0f;
            #pragma unroll
            for (int s = 0; s < 32; ++s) acc += psf[s * 132 + m * 32 + col];
            sh_c[m * 32 + col] = acc;
        }
        __syncthreads();
    };

    // ---- init: hv[m] = emb_tok[x[b0+m,0]] + emb_pos[0] ----
    float hv[M];
    #pragma unroll
    for (int m = 0; m < M; ++m) {
        const int tok = xx[(size_t)(b0 + m) * N];
        hv[m] = emb_tok[(size_t)tok * D + tid] + emb_pos[tid];
    }

    for (int l = 0; l < NL; ++l) {
        // ======== stage A1: v0 = LN1(h) @ wv ========
        layer_norm(hv, ln1_s + l * D, ln1_b + l * D);
        matvecA(sh_y, (const float4*)(wv + (size_t)l * D * D));
        {   // broadcast my v0 chunk to all ranks
            float* dst = cluster.map_shared_rank(sh_v, rk);
            #pragma unroll
            for (int m = 0; m < M; ++m)
                dst[m * D + j0 + lane] = sh_c[m * 32 + lane];
        }
        cluster.sync();

        // ======== stage A2: o = v0 @ wo (chunk), assemble ========
        matvecA(sh_v, (const float4*)(wo + (size_t)l * D * D));
        {
            float* dst = cluster.map_shared_rank(sh_o, rk);
            #pragma unroll
            for (int m = 0; m < M; ++m)
                dst[m * D + j0 + lane] = sh_c[m * 32 + lane];
        }
        cluster.sync();
        #pragma unroll
        for (int m = 0; m < M; ++m)
            hv[m] += sh_o[m * D + tid] + bo[l * D + tid];

        // ======== stage B: hidden = gelu(LN2(h) @ w1 + b1) (my 128 cols) ====
        layer_norm(hv, ln2_s + l * D, ln2_b + l * D);
        {
            const float4* W14 = (const float4*)(w1 + (size_t)l * D * F);
            float4 a[M];
            #pragma unroll
            for (int m = 0; m < M; ++m) a[m] = make_float4(0.f, 0.f, 0.f, 0.f);
            #pragma unroll
            for (int i = 0; i < 32; ++i) {
                int k = ksb * 32 + i;
                float4 w = W14[k * 256 + r * 32 + c4b];
                #pragma unroll
                for (int m = 0; m < M; ++m) {
                    float yk = sh_y[m * D + k];
                    a[m].x = fmaf(yk, w.x, a[m].x); a[m].y = fmaf(yk, w.y, a[m].y);
                    a[m].z = fmaf(yk, w.z, a[m].z); a[m].w = fmaf(yk, w.w, a[m].w);
                }
            }
            #pragma unroll
            for (int m = 0; m < M; ++m) ps4[ksb * 128 + m * 32 + c4b] = a[m];
            __syncthreads();
            #pragma unroll
            for (int t = 0; t < 2; ++t) {
                int o = tid + t * 256;           // 512 outputs = (m, col)
                int m = o >> 7, col = o & 127;
                float acc = b1v[l * F + j0b + col];
                #pragma unroll
                for (int s = 0; s < 8; ++s) acc += psf[s * 512 + m * 128 + col];
                sh_c[m * 128 + col] = gelu_tanh(acc);
            }
            __syncthreads();
            float* dst = cluster.map_shared_rank(sh_g, rk);
            #pragma unroll
            for (int m = 0; m < M; ++m)
                #pragma unroll
                for (int e = 0; e < 4; ++e)
                    dst[m * F + j0b + e * 32 + lane] = sh_c[m * 128 + e * 32 + lane];
        }
        cluster.sync();

        // ======== stage C: delta = hidden @ w2 (chunk), assemble ========
        {
            const float4* W24 = (const float4*)(w2 + (size_t)l * F * D);
            float4 a[M];
            #pragma unroll
            for (int m = 0; m < M; ++m) a[m] = make_float4(0.f, 0.f, 0.f, 0.f);
            #pragma unroll
            for (int i = 0; i < 32; ++i) {
                int k = ks * 32 + i;
                float4 w = W24[k * 64 + r * 8 + c4];
                #pragma unroll
                for (int m = 0; m < M; ++m) {
                    float yk = sh_g[m * F + k];
                    a[m].x = fmaf(yk, w.x, a[m].x); a[m].y = fmaf(yk, w.y, a[m].y);
                    a[m].z = fmaf(yk, w.z, a[m].z); a[m].w = fmaf(yk, w.w, a[m].w);
                }
            }
            #pragma unroll
            for (int m = 0; m < M; ++m) ps4[ks * 33 + m * 8 + c4] = a[m];
            __syncthreads();
            if (tid < 128) {
                int m = tid >> 5, col = tid & 31;
                float acc = 0.0f;
                #pragma unroll
                for (int s = 0; s < 32; ++s) acc += psf[s * 132 + m * 32 + col];
                sh_c[m * 32 + col] = acc;
            }
            __syncthreads();
            float* dst = cluster.map_shared_rank(sh_o, rk);
            #pragma unroll
            for (int m = 0; m < M; ++m)
                dst[m * D + j0 + lane] = sh_c[m * 32 + lane];
        }
        cluster.sync();
        #pragma unroll
        for (int m = 0; m < M; ++m)
            hv[m] += sh_o[m * D + tid] + b2v[l * D + tid];
    }

    // ======== classifier (rank 0 handles its cluster's M batches) ========
    if (r == 0) {
        #pragma unroll
        for (int m = 0; m < M; ++m) sh_y[m * D + tid] = hv[m];
        __syncthreads();
        if (tid < 160) {
            const int c = tid >> 4;              // class 0..9
            const int s = tid & 15;              // 16 K-slices of 16
            #pragma unroll
            for (int m = 0; m < M; ++m) {
                float acc = 0.0f;
                #pragma unroll
                for (int i = 0; i < 16; ++i) {
                    int k = s * 16 + i;
                    acc = fmaf(sh_y[m * D + k], wcls[k * NC + c], acc);
                }
                psf[m * 176 + c * 17 + s] = acc;
            }
        }
        __syncthreads();
        if (tid < NC) {
            #pragma unroll
            for (int m = 0; m < M; ++m) {
                float acc = bcls[tid];
                #pragma unroll
                for (int s = 0; s < 16; ++s) acc += psf[m * 176 + tid * 17 + s];
                out[(size_t)(b0 + m) * NC + tid] = acc;
            }
        }
    }
}

extern "C" void kernel_launch(void* const* d_in, const int* in_sizes, int n_in,
                              void* d_out, int out_size)
{
    const int*   xx      = (const int*)  d_in[0];
    const float* emb_tok = (const float*)d_in[1];
    const float* emb_pos = (const float*)d_in[2];
    const float* ln1_s   = (const float*)d_in[4];
    const float* ln1_b   = (const float*)d_in[5];
    const float* wv      = (const float*)d_in[8];
    const float* wo      = (const float*)d_in[9];
    const float* bo      = (const float*)d_in[10];
    const float* ln2_s   = (const float*)d_in[11];
    const float* ln2_b   = (const float*)d_in[12];
    const float* w1      = (const float*)d_in[13];
    const float* b1v     = (const float*)d_in[14];
    const float* w2      = (const float*)d_in[15];
    const float* b2v     = (const float*)d_in[16];
    const float* wcls    = (const float*)d_in[17];
    const float* bcls    = (const float*)d_in[18];
    float* out = (float*)d_out;

    const int B = out_size / NC;          // 16
    const int N = in_sizes[0] / B;        // 4096
    const int grid = (B / M) * CS;        // 32 blocks = 4 clusters

    performer_cls_kernel<<<grid, TPB>>>(xx, emb_tok, emb_pos, ln1_s, ln1_b,
                                        wv, wo, bo, ln2_s, ln2_b,
                                        w1, b1v, w2, b2v, wcls, bcls, out, N);
}